// round 5
// baseline (speedup 1.0000x reference)
#include <cuda_runtime.h>
#include <cstdint>

#define N_CELLS  8388608
#define N_HALO   1048576
#define NTHREADS 256
#define EPT      4
#define STRIDE   (N_HALO / EPT)                  // 262144
#define NBLOCKS  (N_HALO / (NTHREADS * EPT))     // 1024, exact
#define COARSE_BIT 0x80000000

// Packed per-halo record: .x = i0 | (coarse << 31), .y = i1.  8 MB static.
__device__ int2 g_packed[N_HALO];

// coarse -> 0.5*(a+b), else a. Bit-equivalent to the reference weighting.
__device__ __forceinline__ float interp(bool c, float a, float b) {
    return c ? 0.5f * (a + b) : a;
}

// Branch-free predicated gather: compiles to @P LDG, no BSSY/BSYNC.
__device__ __forceinline__ float gather_if(bool c, const float* __restrict__ f, int i) {
    return c ? __ldg(f + i) : 0.0f;
}

// ---------------------------------------------------------------------------
// Pass 1: consume raw idx+weights, emit packed; gather u, v, eta1.
__global__ __launch_bounds__(NTHREADS) void pass_pack3(
    const float* __restrict__ fa, const float* __restrict__ fb,
    const float* __restrict__ fc,
    const int2* __restrict__ src_idx, const float2* __restrict__ weights,
    float* __restrict__ oa, float* __restrict__ ob, float* __restrict__ oc)
{
    const int t = blockIdx.x * NTHREADS + threadIdx.x;
    int i0[EPT], i1[EPT]; bool c[EPT];
    #pragma unroll
    for (int k = 0; k < EPT; k++) {
        const int e = t + k * STRIDE;
        const int2   i = __ldcs(src_idx + e);
        const float2 w = __ldcs(weights + e);
        c[k]  = (w.y != 0.0f);
        i0[k] = i.x; i1[k] = i.y;
        g_packed[e] = make_int2(i.x | (c[k] ? COARSE_BIT : 0), i.y);
    }
    float a0[EPT], b0[EPT], c0[EPT], a1[EPT], b1[EPT], c1[EPT];
    #pragma unroll
    for (int k = 0; k < EPT; k++) {
        a0[k] = __ldg(fa + i0[k]); b0[k] = __ldg(fb + i0[k]); c0[k] = __ldg(fc + i0[k]);
    }
    #pragma unroll
    for (int k = 0; k < EPT; k++) {
        a1[k] = gather_if(c[k], fa, i1[k]);
        b1[k] = gather_if(c[k], fb, i1[k]);
        c1[k] = gather_if(c[k], fc, i1[k]);
    }
    #pragma unroll
    for (int k = 0; k < EPT; k++) {
        const int e = t + k * STRIDE;
        __stcs(oa + e, interp(c[k], a0[k], a1[k]));
        __stcs(ob + e, interp(c[k], b0[k], b1[k]));
        __stcs(oc + e, interp(c[k], c0[k], c1[k]));
    }
}

// ---------------------------------------------------------------------------
// Generic 2-field pass (reads packed).
__global__ __launch_bounds__(NTHREADS) void pass2(
    const float* __restrict__ fa, const float* __restrict__ fb,
    float* __restrict__ oa, float* __restrict__ ob)
{
    const int t = blockIdx.x * NTHREADS + threadIdx.x;
    int i0[EPT], i1[EPT]; bool c[EPT];
    #pragma unroll
    for (int k = 0; k < EPT; k++) {
        const int2 p = __ldcs(&g_packed[t + k * STRIDE]);
        c[k]  = (p.x & COARSE_BIT) != 0;
        i0[k] = p.x & ~COARSE_BIT;
        i1[k] = p.y;
    }
    float a0[EPT], b0[EPT], a1[EPT], b1[EPT];
    #pragma unroll
    for (int k = 0; k < EPT; k++) { a0[k] = __ldg(fa + i0[k]); b0[k] = __ldg(fb + i0[k]); }
    #pragma unroll
    for (int k = 0; k < EPT; k++) {
        a1[k] = gather_if(c[k], fa, i1[k]);
        b1[k] = gather_if(c[k], fb, i1[k]);
    }
    #pragma unroll
    for (int k = 0; k < EPT; k++) {
        const int e = t + k * STRIDE;
        __stcs(oa + e, interp(c[k], a0[k], a1[k]));
        __stcs(ob + e, interp(c[k], b0[k], b1[k]));
    }
}

// ---------------------------------------------------------------------------
// h, Hb -> row4 (h) and row7 (h+Hb, per-cell sum before interpolation).
__global__ __launch_bounds__(NTHREADS) void pass_h(
    const float* __restrict__ hf, const float* __restrict__ Hbf,
    float* __restrict__ o4, float* __restrict__ o7)
{
    const int t = blockIdx.x * NTHREADS + threadIdx.x;
    int i0[EPT], i1[EPT]; bool c[EPT];
    #pragma unroll
    for (int k = 0; k < EPT; k++) {
        const int2 p = __ldcs(&g_packed[t + k * STRIDE]);
        c[k]  = (p.x & COARSE_BIT) != 0;
        i0[k] = p.x & ~COARSE_BIT;
        i1[k] = p.y;
    }
    float h0[EPT], H0[EPT], h1[EPT], H1[EPT];
    #pragma unroll
    for (int k = 0; k < EPT; k++) { h0[k] = __ldg(hf + i0[k]); H0[k] = __ldg(Hbf + i0[k]); }
    #pragma unroll
    for (int k = 0; k < EPT; k++) {
        h1[k] = gather_if(c[k], hf, i1[k]);
        H1[k] = gather_if(c[k], Hbf, i1[k]);
    }
    #pragma unroll
    for (int k = 0; k < EPT; k++) {
        const int e = t + k * STRIDE;
        __stcs(o4 + e, interp(c[k], h0[k], h1[k]));
        __stcs(o7 + e, interp(c[k], h0[k] + H0[k], h1[k] + H1[k]));
    }
}

// ---------------------------------------------------------------------------
// k_u, k_v, k3 -> rows 9, 10 with per-cell min before interpolation.
__global__ __launch_bounds__(NTHREADS) void pass_min(
    const float* __restrict__ ku, const float* __restrict__ kv,
    const float* __restrict__ k3,
    float* __restrict__ o9, float* __restrict__ o10)
{
    const int t = blockIdx.x * NTHREADS + threadIdx.x;
    int i0[EPT], i1[EPT]; bool c[EPT];
    #pragma unroll
    for (int k = 0; k < EPT; k++) {
        const int2 p = __ldcs(&g_packed[t + k * STRIDE]);
        c[k]  = (p.x & COARSE_BIT) != 0;
        i0[k] = p.x & ~COARSE_BIT;
        i1[k] = p.y;
    }
    float u0[EPT], v0[EPT], w0[EPT], u1[EPT], v1[EPT], w1[EPT];
    #pragma unroll
    for (int k = 0; k < EPT; k++) {
        u0[k] = __ldg(ku + i0[k]); v0[k] = __ldg(kv + i0[k]); w0[k] = __ldg(k3 + i0[k]);
    }
    #pragma unroll
    for (int k = 0; k < EPT; k++) {
        u1[k] = gather_if(c[k], ku, i1[k]);
        v1[k] = gather_if(c[k], kv, i1[k]);
        w1[k] = gather_if(c[k], k3, i1[k]);
    }
    #pragma unroll
    for (int k = 0; k < EPT; k++) {
        const int e = t + k * STRIDE;
        __stcs(o9  + e, interp(c[k], fminf(u0[k], w0[k]), fminf(u1[k], w1[k])));
        __stcs(o10 + e, interp(c[k], fminf(v0[k], w0[k]), fminf(v1[k], w1[k])));
    }
}

extern "C" void kernel_launch(void* const* d_in, const int* in_sizes, int n_in,
                              void* d_out, int out_size)
{
    const float*  fields  = (const float*)d_in[0];
    const int2*   src_idx = (const int2*)d_in[1];
    const float2* weights = (const float2*)d_in[2];
    float*        out     = (float*)d_out;

    // Inputs: 0:u 1:v 2:b_u 3:b_v 4:h 5:Hb 6:hh 7:dif_h 8:eta1 9:k_u 10:k_v 11:k3
    const float* F[12];
    for (int f = 0; f < 12; f++) F[f] = fields + (size_t)f * N_CELLS;
    float* O[11];
    for (int q = 0; q < 11; q++) O[q] = out + (size_t)q * N_HALO;

    pass_pack3<<<NBLOCKS, NTHREADS>>>(F[0], F[1], F[8], src_idx, weights,
                                      O[0], O[1], O[8]);        // u, v, eta1
    pass2     <<<NBLOCKS, NTHREADS>>>(F[2], F[3], O[2], O[3]);  // b_u, b_v
    pass_h    <<<NBLOCKS, NTHREADS>>>(F[4], F[5], O[4], O[7]);  // h, Hb
    pass2     <<<NBLOCKS, NTHREADS>>>(F[6], F[7], O[5], O[6]);  // hh, dif_h
    pass_min  <<<NBLOCKS, NTHREADS>>>(F[9], F[10], F[11], O[9], O[10]); // k_u,k_v,k3
}

// round 6
// speedup vs baseline: 1.0121x; 1.0121x over previous
#include <cuda_runtime.h>
#include <cstdint>

#define N_CELLS  8388608
#define N_HALO   1048576
#define NTHREADS 256
#define EPT      4
#define STRIDE   (N_HALO / EPT)                  // 262144
#define NBLOCKS  (N_HALO / (NTHREADS * EPT))     // 1024, exact
#define COARSE_BIT 0x80000000

// Packed per-halo record: .x = i0 | (coarse << 31), .y = i1.  8 MB static.
__device__ int2 g_packed[N_HALO];

// coarse -> 0.5*(a+b), else a. Bit-equivalent to the reference weighting.
__device__ __forceinline__ float interp(bool c, float a, float b) {
    return c ? 0.5f * (a + b) : a;
}

// Branch-free predicated gather: compiles to @P LDG, no BSSY/BSYNC.
__device__ __forceinline__ float gather_if(bool c, const float* __restrict__ f, int i) {
    return c ? __ldg(f + i) : 0.0f;
}

// ---------------------------------------------------------------------------
// Pass 1: consume raw idx+weights, emit packed; gather u, v, eta1.
__global__ __launch_bounds__(NTHREADS) void pass_pack3(
    const float* __restrict__ fa, const float* __restrict__ fb,
    const float* __restrict__ fc,
    const int2* __restrict__ src_idx, const float2* __restrict__ weights,
    float* __restrict__ oa, float* __restrict__ ob, float* __restrict__ oc)
{
    const int t = blockIdx.x * NTHREADS + threadIdx.x;
    int i0[EPT], i1[EPT]; bool c[EPT];
    #pragma unroll
    for (int k = 0; k < EPT; k++) {
        const int e = t + k * STRIDE;
        const int2   i = __ldcs(src_idx + e);
        const float2 w = __ldcs(weights + e);
        c[k]  = (w.y != 0.0f);
        i0[k] = i.x; i1[k] = i.y;
        g_packed[e] = make_int2(i.x | (c[k] ? COARSE_BIT : 0), i.y);
    }
    float a0[EPT], b0[EPT], c0[EPT], a1[EPT], b1[EPT], c1[EPT];
    #pragma unroll
    for (int k = 0; k < EPT; k++) {
        a0[k] = __ldg(fa + i0[k]); b0[k] = __ldg(fb + i0[k]); c0[k] = __ldg(fc + i0[k]);
    }
    #pragma unroll
    for (int k = 0; k < EPT; k++) {
        a1[k] = gather_if(c[k], fa, i1[k]);
        b1[k] = gather_if(c[k], fb, i1[k]);
        c1[k] = gather_if(c[k], fc, i1[k]);
    }
    #pragma unroll
    for (int k = 0; k < EPT; k++) {
        const int e = t + k * STRIDE;
        __stcs(oa + e, interp(c[k], a0[k], a1[k]));
        __stcs(ob + e, interp(c[k], b0[k], b1[k]));
        __stcs(oc + e, interp(c[k], c0[k], c1[k]));
    }
}

// ---------------------------------------------------------------------------
// Generic 2-field pass (reads packed).
__global__ __launch_bounds__(NTHREADS) void pass2(
    const float* __restrict__ fa, const float* __restrict__ fb,
    float* __restrict__ oa, float* __restrict__ ob)
{
    const int t = blockIdx.x * NTHREADS + threadIdx.x;
    int i0[EPT], i1[EPT]; bool c[EPT];
    #pragma unroll
    for (int k = 0; k < EPT; k++) {
        const int2 p = __ldcs(&g_packed[t + k * STRIDE]);
        c[k]  = (p.x & COARSE_BIT) != 0;
        i0[k] = p.x & ~COARSE_BIT;
        i1[k] = p.y;
    }
    float a0[EPT], b0[EPT], a1[EPT], b1[EPT];
    #pragma unroll
    for (int k = 0; k < EPT; k++) { a0[k] = __ldg(fa + i0[k]); b0[k] = __ldg(fb + i0[k]); }
    #pragma unroll
    for (int k = 0; k < EPT; k++) {
        a1[k] = gather_if(c[k], fa, i1[k]);
        b1[k] = gather_if(c[k], fb, i1[k]);
    }
    #pragma unroll
    for (int k = 0; k < EPT; k++) {
        const int e = t + k * STRIDE;
        __stcs(oa + e, interp(c[k], a0[k], a1[k]));
        __stcs(ob + e, interp(c[k], b0[k], b1[k]));
    }
}

// ---------------------------------------------------------------------------
// h, Hb -> row4 (h) and row7 (h+Hb, per-cell sum before interpolation).
__global__ __launch_bounds__(NTHREADS) void pass_h(
    const float* __restrict__ hf, const float* __restrict__ Hbf,
    float* __restrict__ o4, float* __restrict__ o7)
{
    const int t = blockIdx.x * NTHREADS + threadIdx.x;
    int i0[EPT], i1[EPT]; bool c[EPT];
    #pragma unroll
    for (int k = 0; k < EPT; k++) {
        const int2 p = __ldcs(&g_packed[t + k * STRIDE]);
        c[k]  = (p.x & COARSE_BIT) != 0;
        i0[k] = p.x & ~COARSE_BIT;
        i1[k] = p.y;
    }
    float h0[EPT], H0[EPT], h1[EPT], H1[EPT];
    #pragma unroll
    for (int k = 0; k < EPT; k++) { h0[k] = __ldg(hf + i0[k]); H0[k] = __ldg(Hbf + i0[k]); }
    #pragma unroll
    for (int k = 0; k < EPT; k++) {
        h1[k] = gather_if(c[k], hf, i1[k]);
        H1[k] = gather_if(c[k], Hbf, i1[k]);
    }
    #pragma unroll
    for (int k = 0; k < EPT; k++) {
        const int e = t + k * STRIDE;
        __stcs(o4 + e, interp(c[k], h0[k], h1[k]));
        __stcs(o7 + e, interp(c[k], h0[k] + H0[k], h1[k] + H1[k]));
    }
}

// ---------------------------------------------------------------------------
// k_u, k_v, k3 -> rows 9, 10 with per-cell min before interpolation.
__global__ __launch_bounds__(NTHREADS) void pass_min(
    const float* __restrict__ ku, const float* __restrict__ kv,
    const float* __restrict__ k3,
    float* __restrict__ o9, float* __restrict__ o10)
{
    const int t = blockIdx.x * NTHREADS + threadIdx.x;
    int i0[EPT], i1[EPT]; bool c[EPT];
    #pragma unroll
    for (int k = 0; k < EPT; k++) {
        const int2 p = __ldcs(&g_packed[t + k * STRIDE]);
        c[k]  = (p.x & COARSE_BIT) != 0;
        i0[k] = p.x & ~COARSE_BIT;
        i1[k] = p.y;
    }
    float u0[EPT], v0[EPT], w0[EPT], u1[EPT], v1[EPT], w1[EPT];
    #pragma unroll
    for (int k = 0; k < EPT; k++) {
        u0[k] = __ldg(ku + i0[k]); v0[k] = __ldg(kv + i0[k]); w0[k] = __ldg(k3 + i0[k]);
    }
    #pragma unroll
    for (int k = 0; k < EPT; k++) {
        u1[k] = gather_if(c[k], ku, i1[k]);
        v1[k] = gather_if(c[k], kv, i1[k]);
        w1[k] = gather_if(c[k], k3, i1[k]);
    }
    #pragma unroll
    for (int k = 0; k < EPT; k++) {
        const int e = t + k * STRIDE;
        __stcs(o9  + e, interp(c[k], fminf(u0[k], w0[k]), fminf(u1[k], w1[k])));
        __stcs(o10 + e, interp(c[k], fminf(v0[k], w0[k]), fminf(v1[k], w1[k])));
    }
}

extern "C" void kernel_launch(void* const* d_in, const int* in_sizes, int n_in,
                              void* d_out, int out_size)
{
    const float*  fields  = (const float*)d_in[0];
    const int2*   src_idx = (const int2*)d_in[1];
    const float2* weights = (const float2*)d_in[2];
    float*        out     = (float*)d_out;

    // Inputs: 0:u 1:v 2:b_u 3:b_v 4:h 5:Hb 6:hh 7:dif_h 8:eta1 9:k_u 10:k_v 11:k3
    const float* F[12];
    for (int f = 0; f < 12; f++) F[f] = fields + (size_t)f * N_CELLS;
    float* O[11];
    for (int q = 0; q < 11; q++) O[q] = out + (size_t)q * N_HALO;

    pass_pack3<<<NBLOCKS, NTHREADS>>>(F[0], F[1], F[8], src_idx, weights,
                                      O[0], O[1], O[8]);        // u, v, eta1
    pass2     <<<NBLOCKS, NTHREADS>>>(F[2], F[3], O[2], O[3]);  // b_u, b_v
    pass_h    <<<NBLOCKS, NTHREADS>>>(F[4], F[5], O[4], O[7]);  // h, Hb
    pass2     <<<NBLOCKS, NTHREADS>>>(F[6], F[7], O[5], O[6]);  // hh, dif_h
    pass_min  <<<NBLOCKS, NTHREADS>>>(F[9], F[10], F[11], O[9], O[10]); // k_u,k_v,k3
}